// round 5
// baseline (speedup 1.0000x reference)
#include <cuda_runtime.h>

// EctLayer: out[g, s, t] = sum over points n with index[n]==g of
//           sigmoid(500*(lin[s] - dot(x[n], v[:,t])))
// Shapes: x[N,3] f32, v[3,32] f32, lin[32,1,1] f32, index[N] (sorted,
// int32 or int64), out[128,32,32] f32.
//
// Algorithm: 500*(lin[1]-lin[0]) ~= 35.5, so for each (n,t) only the step
// nearest to nh is fractional; every other step's sigmoid is 0 or 1 to
// within ~2e-8. Accumulate in the step-difference domain: d[sf] += frac,
// d[sf+1] += 1-frac (2 warp-private, conflict-free SMEM updates per pair),
// then prefix-sum over steps in the epilogue. The 0/1 truncation error
// telescopes exactly in the prefix sum; accuracy is set by the one exact
// sigmoid per pair.

#define NUM_T 32
#define NUM_S 32
#define NROWS 33                          // 32 real rows + 1 trash row
#define NW 32                             // warps per CTA
#define NTHREADS (NW * 32)
#define COPY_ELEMS (NROWS * NUM_T)        // 1056 floats per warp copy
#define ACC_ELEMS (NW * COPY_ELEMS)       // 33792 floats = 132 KB

// Warp-collective 32-ary lower_bound over sorted non-negative ints.
// stride=1 for int32, stride=2 for int64 (low words only; values < 2^31).
__device__ __forceinline__ int warp_lower_bound(const int* __restrict__ a,
                                                int stride, int n, int key)
{
    const int lane = threadIdx.x & 31;
    int lo = 0, hi = n;                   // answer in [lo, hi]
    while (hi > lo) {
        const int len = hi - lo;
        if (len <= 32) {
            int val = (lane < len) ? a[(lo + lane) * stride] : 0x7fffffff;
            unsigned bal = __ballot_sync(0xffffffffu, val < key);
            return lo + __popc(bal);
        }
        // 32 probes split [lo,hi) into 33 chunks; predicate is monotone.
        int pos = lo + (int)(((long long)(lane + 1) * len) / 33);
        int val = a[pos * stride];
        unsigned bal = __ballot_sync(0xffffffffu, val < key);
        int k = __popc(bal);              // first k probes have val < key
        int nlo = (k == 0)  ? lo : lo + (int)(((long long)k * len) / 33) + 1;
        int nhi = (k == 32) ? hi : lo + (int)(((long long)(k + 1) * len) / 33);
        lo = nlo; hi = nhi;
    }
    return lo;
}

__global__ __launch_bounds__(NTHREADS, 1)
void ect_kernel(const float* __restrict__ x,
                const float* __restrict__ v,
                const float* __restrict__ lin,
                const int* __restrict__ idx32,
                float* __restrict__ out,
                int npts)
{
    extern __shared__ float acc[];        // NW warp-private [33 x 32] copies
    __shared__ int segS[2];

    const int g    = blockIdx.x;
    const int tid  = threadIdx.x;
    const int w    = tid >> 5;
    const int lane = tid & 31;

    // Detect index dtype. int64 little-endian: word[npts-1] (odd position,
    // npts even) is a high word == 0 while word[npts-2] is a mid-array low
    // word != 0. int32: word[npts-1] is the last (max) sorted index != 0.
    const bool is64   = (idx32[npts - 1] == 0) && (idx32[npts - 2] != 0);
    const int  stride = is64 ? 2 : 1;

    // Overlap: warps 0/1 find this graph's [s0,s1) while warps 2..31 zero
    // the 132 KB accumulator with float4 stores.
    if (w == 0) {
        int a = warp_lower_bound(idx32, stride, npts, g);
        if (lane == 0) segS[0] = a;
    } else if (w == 1) {
        int b = warp_lower_bound(idx32, stride, npts, g + 1);
        if (lane == 0) segS[1] = b;
    } else {
        float4* acc4 = (float4*)acc;
        for (int i = tid - 64; i < ACC_ELEMS / 4; i += NTHREADS - 64)
            acc4[i] = make_float4(0.f, 0.f, 0.f, 0.f);
    }
    __syncthreads();

    // Per-lane direction (lane == theta); v is [3, 32] row-major.
    const float v0 = __ldg(v + lane);
    const float v1 = __ldg(v + NUM_T + lane);
    const float v2 = __ldg(v + 2 * NUM_T + lane);
    const float l0   = __ldg(lin);
    const float step = __ldg(lin + 1) - l0;
    const float invStep  = 1.0f / step;
    const float negl0inv = -l0 * invStep;
    // z*log2(e) = A*sff + (B - A2*nh), where z = 500*(l0 + sff*step - nh)
    const float A2 = 500.0f * 1.4426950408889634f;
    const float A  = A2 * step;
    const float B  = A2 * l0;

    float* my = acc + w * COPY_ELEMS + lane;   // lane-owned column

    const int s0 = segS[0], s1 = segS[1];

    // Main loop, unrolled x2 over points: warp w owns points
    // {s0+w, s0+w+32, s0+w+64, ...}; one iteration handles a pair (p, p+NW).
    // All lanes broadcast-load the same point -> 1 request per LDG. Loads
    // are index-clamped (always in-bounds); only the accumulate of the
    // second point is predicated (warp-uniform predicate).
    if (s0 < s1) {
        const int last3 = (s1 - 1) * 3;
        int p = s0 + w;

        int pa = min(p * 3, last3);
        int pb = min((p + NW) * 3, last3);
        float a0 = __ldg(x + pa), a1 = __ldg(x + pa + 1), a2 = __ldg(x + pa + 2);
        float b0 = __ldg(x + pb), b1 = __ldg(x + pb + 1), b2 = __ldg(x + pb + 2);

        while (p < s1) {
            const int pn  = p + 2 * NW;
            const int pna = min(pn * 3, last3);
            const int pnb = min((pn + NW) * 3, last3);
            const float na0 = __ldg(x + pna), na1 = __ldg(x + pna + 1), na2 = __ldg(x + pna + 2);
            const float nb0 = __ldg(x + pnb), nb1 = __ldg(x + pnb + 1), nb2 = __ldg(x + pnb + 2);

            // Point A (always valid: p < s1)
            const float nhA  = fmaf(a2, v2, fmaf(a1, v1, a0 * v0));
            const float uA   = fmaf(nhA, invStep, negl0inv);
            const float sffA = fminf(31.0f, fmaxf(0.0f, rintf(uA)));
            const float zA   = fmaf(sffA, A, fmaf(-A2, nhA, B));
            // Point B (valid iff p+NW < s1; data clamped so math is safe)
            const float nhB  = fmaf(b2, v2, fmaf(b1, v1, b0 * v0));
            const float uB   = fmaf(nhB, invStep, negl0inv);
            const float sffB = fminf(31.0f, fmaxf(0.0f, rintf(uB)));
            const float zB   = fmaf(sffB, A, fmaf(-A2, nhB, B));

            // Two independent MUFU chains in flight.
            const float eA = exp2f(-zA);
            const float eB = exp2f(-zB);
            const float fracA = __fdividef(1.0f, 1.0f + eA);
            const float fracB = __fdividef(1.0f, 1.0f + eB);

            // Difference-domain accumulation. Lane exclusively owns its
            // column of this warp's copy: no atomics, bank == lane,
            // conflict-free. Row sf+1 always valid (row 32 = trash).
            {
                float* rowp = my + (int)sffA * NUM_T;
                rowp[0]     += fracA;
                rowp[NUM_T] += 1.0f - fracA;
            }
            if (p + NW < s1) {            // warp-uniform branch
                float* rowp = my + (int)sffB * NUM_T;
                rowp[0]     += fracB;
                rowp[NUM_T] += 1.0f - fracB;
            }

            a0 = na0; a1 = na1; a2 = na2;
            b0 = nb0; b1 = nb1; b2 = nb2;
            p = pn;
        }
    }
    __syncthreads();

    // Epilogue: tid -> (s = w, t = lane). Reduce the NW warp copies of
    // element (s,t), then prefix-sum over s to undo the difference domain.
    {
        const int s = w, t = lane;
        float sum = 0.0f;
        #pragma unroll
        for (int wi = 0; wi < NW; wi++)
            sum += acc[wi * COPY_ELEMS + s * NUM_T + t];
        acc[s * NUM_T + t] = sum;         // own slot of copy 0; barrier below
        __syncthreads();

        float o = 0.0f;
        #pragma unroll
        for (int sp = 0; sp < NUM_S; sp++)
            if (sp <= s) o += acc[sp * NUM_T + t];
        out[g * (NUM_S * NUM_T) + tid] = o;   // tid == s*32 + t, coalesced
    }
}

extern "C" void kernel_launch(void* const* d_in, const int* in_sizes, int n_in,
                              void* d_out, int out_size)
{
    const float* x   = (const float*)d_in[0];
    const float* v   = (const float*)d_in[1];
    const float* lin = (const float*)d_in[2];
    const int*   idx = (const int*)d_in[3];
    float*       out = (float*)d_out;
    const int npts = in_sizes[0] / 3;
    const int numG = out_size / (NUM_S * NUM_T);

    cudaFuncSetAttribute(ect_kernel,
                         cudaFuncAttributeMaxDynamicSharedMemorySize,
                         ACC_ELEMS * (int)sizeof(float));
    ect_kernel<<<numG, NTHREADS, ACC_ELEMS * sizeof(float)>>>(x, v, lin, idx, out, npts);
}

// round 6
// speedup vs baseline: 1.0019x; 1.0019x over previous
#include <cuda_runtime.h>

// EctLayer: out[g, s, t] = sum over points n with index[n]==g of
//           sigmoid(500*(lin[s] - dot(x[n], v[:,t])))
// Shapes: x[N,3] f32, v[3,32] f32, lin[32,1,1] f32, index[N] (sorted,
// int32 or int64), out[128,32,32] f32.
//
// Algorithm: 500*(lin[1]-lin[0]) ~= 35.5, so for each (n,t) only the step
// nearest to nh is fractional; every other step's sigmoid is 0 or 1 to
// within ~2e-8. Accumulate in the step-difference domain: d[sf] += frac,
// d[sf+1] += 1-frac (2 warp-private, conflict-free SMEM updates per pair),
// then prefix-sum over steps in the epilogue. Truncation telescopes exactly.
//
// R5 ncu: issue=51.8%, occ=50.8%, no pipe >32% -> latency-bound. This rev:
// unroll x4 over points for 4 independent LDG/MUFU/SMEM-RMW chains per warp.

#define NUM_T 32
#define NUM_S 32
#define NROWS 33                          // 32 real rows + 1 trash row
#define NW 32                             // warps per CTA
#define NTHREADS (NW * 32)
#define COPY_ELEMS (NROWS * NUM_T)        // 1056 floats per warp copy
#define ACC_ELEMS (NW * COPY_ELEMS)       // 33792 floats = 132 KB

// Warp-collective 32-ary lower_bound over sorted non-negative ints.
// stride=1 for int32, stride=2 for int64 (low words only; values < 2^31).
__device__ __forceinline__ int warp_lower_bound(const int* __restrict__ a,
                                                int stride, int n, int key)
{
    const int lane = threadIdx.x & 31;
    int lo = 0, hi = n;
    while (hi > lo) {
        const int len = hi - lo;
        if (len <= 32) {
            int val = (lane < len) ? a[(lo + lane) * stride] : 0x7fffffff;
            unsigned bal = __ballot_sync(0xffffffffu, val < key);
            return lo + __popc(bal);
        }
        int pos = lo + (int)(((long long)(lane + 1) * len) / 33);
        int val = a[pos * stride];
        unsigned bal = __ballot_sync(0xffffffffu, val < key);
        int k = __popc(bal);
        int nlo = (k == 0)  ? lo : lo + (int)(((long long)k * len) / 33) + 1;
        int nhi = (k == 32) ? hi : lo + (int)(((long long)(k + 1) * len) / 33);
        lo = nlo; hi = nhi;
    }
    return lo;
}

__global__ __launch_bounds__(NTHREADS, 1)
void ect_kernel(const float* __restrict__ x,
                const float* __restrict__ v,
                const float* __restrict__ lin,
                const int* __restrict__ idx32,
                float* __restrict__ out,
                int npts)
{
    extern __shared__ float acc[];        // NW warp-private [33 x 32] copies
    __shared__ int segS[2];

    const int g    = blockIdx.x;
    const int tid  = threadIdx.x;
    const int w    = tid >> 5;
    const int lane = tid & 31;

    // Detect index dtype (int64 little-endian high word of last element is 0).
    const bool is64   = (idx32[npts - 1] == 0) && (idx32[npts - 2] != 0);
    const int  stride = is64 ? 2 : 1;

    // Warps 0/1 find [s0,s1); warps 2..31 zero the 132 KB accumulator.
    if (w == 0) {
        int a = warp_lower_bound(idx32, stride, npts, g);
        if (lane == 0) segS[0] = a;
    } else if (w == 1) {
        int b = warp_lower_bound(idx32, stride, npts, g + 1);
        if (lane == 0) segS[1] = b;
    } else {
        float4* acc4 = (float4*)acc;
        for (int i = tid - 64; i < ACC_ELEMS / 4; i += NTHREADS - 64)
            acc4[i] = make_float4(0.f, 0.f, 0.f, 0.f);
    }
    __syncthreads();

    // Per-lane direction (lane == theta); v is [3, 32] row-major.
    const float v0 = __ldg(v + lane);
    const float v1 = __ldg(v + NUM_T + lane);
    const float v2 = __ldg(v + 2 * NUM_T + lane);
    const float l0   = __ldg(lin);
    const float step = __ldg(lin + 1) - l0;
    const float invStep  = 1.0f / step;
    const float negl0inv = -l0 * invStep;
    // z*log2(e) = A*sff + (B - A2*nh), z = 500*(l0 + sff*step - nh)
    const float A2 = 500.0f * 1.4426950408889634f;
    const float A  = A2 * step;
    const float B  = A2 * l0;

    float* my = acc + w * COPY_ELEMS + lane;   // lane-owned column

    const int s0 = segS[0], s1 = segS[1];

    // Main loop, unrolled x4: warp w handles points {s0+w, s0+w+32, ...};
    // one iteration processes (p, p+NW, p+2NW, p+3NW) as 4 independent
    // chains. All lanes broadcast-load the same point (1 req per LDG).
    // Prefetch indices are clamped in-bounds; accumulates of points B/C/D
    // are predicated (warp-uniform). Row sf+1 always valid (row 32 trash).
    if (s0 < s1) {
        const int last3 = (s1 - 1) * 3;
        int p = s0 + w;

        int ia = min(p * 3, last3);
        int ib = min((p + NW) * 3, last3);
        int ic = min((p + 2 * NW) * 3, last3);
        int id = min((p + 3 * NW) * 3, last3);
        float a0 = __ldg(x + ia), a1 = __ldg(x + ia + 1), a2 = __ldg(x + ia + 2);
        float b0 = __ldg(x + ib), b1 = __ldg(x + ib + 1), b2 = __ldg(x + ib + 2);
        float c0 = __ldg(x + ic), c1 = __ldg(x + ic + 1), c2 = __ldg(x + ic + 2);
        float d0 = __ldg(x + id), d1 = __ldg(x + id + 1), d2 = __ldg(x + id + 2);

        while (p < s1) {
            const int pn  = p + 4 * NW;
            const int na  = min(pn * 3, last3);
            const int nb  = min((pn + NW) * 3, last3);
            const int nc  = min((pn + 2 * NW) * 3, last3);
            const int nd  = min((pn + 3 * NW) * 3, last3);
            const float pa0 = __ldg(x + na), pa1 = __ldg(x + na + 1), pa2 = __ldg(x + na + 2);
            const float pb0 = __ldg(x + nb), pb1 = __ldg(x + nb + 1), pb2 = __ldg(x + nb + 2);
            const float pc0 = __ldg(x + nc), pc1 = __ldg(x + nc + 1), pc2 = __ldg(x + nc + 2);
            const float pd0 = __ldg(x + nd), pd1 = __ldg(x + nd + 1), pd2 = __ldg(x + nd + 2);

            const float nhA = fmaf(a2, v2, fmaf(a1, v1, a0 * v0));
            const float nhB = fmaf(b2, v2, fmaf(b1, v1, b0 * v0));
            const float nhC = fmaf(c2, v2, fmaf(c1, v1, c0 * v0));
            const float nhD = fmaf(d2, v2, fmaf(d1, v1, d0 * v0));

            const float sffA = fminf(31.0f, fmaxf(0.0f, rintf(fmaf(nhA, invStep, negl0inv))));
            const float sffB = fminf(31.0f, fmaxf(0.0f, rintf(fmaf(nhB, invStep, negl0inv))));
            const float sffC = fminf(31.0f, fmaxf(0.0f, rintf(fmaf(nhC, invStep, negl0inv))));
            const float sffD = fminf(31.0f, fmaxf(0.0f, rintf(fmaf(nhD, invStep, negl0inv))));

            const float eA = exp2f(-fmaf(sffA, A, fmaf(-A2, nhA, B)));
            const float eB = exp2f(-fmaf(sffB, A, fmaf(-A2, nhB, B)));
            const float eC = exp2f(-fmaf(sffC, A, fmaf(-A2, nhC, B)));
            const float eD = exp2f(-fmaf(sffD, A, fmaf(-A2, nhD, B)));

            const float fracA = __fdividef(1.0f, 1.0f + eA);
            const float fracB = __fdividef(1.0f, 1.0f + eB);
            const float fracC = __fdividef(1.0f, 1.0f + eC);
            const float fracD = __fdividef(1.0f, 1.0f + eD);

            {   // point A always valid (p < s1)
                float* rowp = my + (int)sffA * NUM_T;
                rowp[0]     += fracA;
                rowp[NUM_T] += 1.0f - fracA;
            }
            if (p + NW < s1) {
                float* rowp = my + (int)sffB * NUM_T;
                rowp[0]     += fracB;
                rowp[NUM_T] += 1.0f - fracB;
            }
            if (p + 2 * NW < s1) {
                float* rowp = my + (int)sffC * NUM_T;
                rowp[0]     += fracC;
                rowp[NUM_T] += 1.0f - fracC;
            }
            if (p + 3 * NW < s1) {
                float* rowp = my + (int)sffD * NUM_T;
                rowp[0]     += fracD;
                rowp[NUM_T] += 1.0f - fracD;
            }

            a0 = pa0; a1 = pa1; a2 = pa2;
            b0 = pb0; b1 = pb1; b2 = pb2;
            c0 = pc0; c1 = pc1; c2 = pc2;
            d0 = pd0; d1 = pd1; d2 = pd2;
            p = pn;
        }
    }
    __syncthreads();

    // Epilogue: tid -> (s = w, t = lane). Reduce the NW warp copies of
    // element (s,t), then prefix-sum over s to undo the difference domain.
    {
        const int s = w, t = lane;
        float sum = 0.0f;
        #pragma unroll
        for (int wi = 0; wi < NW; wi++)
            sum += acc[wi * COPY_ELEMS + s * NUM_T + t];
        acc[s * NUM_T + t] = sum;         // own slot of copy 0; barrier below
        __syncthreads();

        float o = 0.0f;
        #pragma unroll
        for (int sp = 0; sp < NUM_S; sp++)
            if (sp <= s) o += acc[sp * NUM_T + t];
        out[g * (NUM_S * NUM_T) + tid] = o;   // tid == s*32 + t, coalesced
    }
}

extern "C" void kernel_launch(void* const* d_in, const int* in_sizes, int n_in,
                              void* d_out, int out_size)
{
    const float* x   = (const float*)d_in[0];
    const float* v   = (const float*)d_in[1];
    const float* lin = (const float*)d_in[2];
    const int*   idx = (const int*)d_in[3];
    float*       out = (float*)d_out;
    const int npts = in_sizes[0] / 3;
    const int numG = out_size / (NUM_S * NUM_T);

    cudaFuncSetAttribute(ect_kernel,
                         cudaFuncAttributeMaxDynamicSharedMemorySize,
                         ACC_ELEMS * (int)sizeof(float));
    ect_kernel<<<numG, NTHREADS, ACC_ELEMS * sizeof(float)>>>(x, v, lin, idx, out, npts);
}